// round 5
// baseline (speedup 1.0000x reference)
#include <cuda_runtime.h>
#include <math.h>

typedef unsigned long long ull;

// ---------------- device scratch (no allocations allowed) ----------------
__device__ __align__(16) float g_sub[256];
__device__ __align__(16) float g_gi0[768];
__device__ __align__(16) float g_gh0[768];
__device__ __align__(16) float g_r0[256];
__device__ __align__(16) float g_gi[768];          // gi = r0 @ W_ih^T + b_ih (broadcast for all edges)
__device__ __align__(16) float g_gh[1024 * 768];   // per-relation gh table
__device__ __align__(16) float g_rj[1024 * 256];   // per-relation rj table
__device__ __align__(16) float g_obj[1024 * 256];  // per-relation obj table

__device__ __forceinline__ float warp_reduce(float v) {
#pragma unroll
    for (int o = 16; o; o >>= 1) v += __shfl_xor_sync(0xffffffffu, v, o);
    return v;
}
__device__ __forceinline__ float sigmoidf_(float x) { return 1.0f / (1.0f + expf(-x)); }

// packed fp32x2 FMA (2x FFMA rate on sm_103a; only reachable via PTX)
#define FMA2(c, a, b) asm("fma.rn.f32x2 %0, %1, %2, %0;" : "+l"(c) : "l"(a), "l"(b))

// ---------------- K1: sub = tanh(mask@subW^T+subb); gi0 = enc@Wih^T+bih ----------------
// 1024 warps, warp-per-output dot (len 256).
__global__ __launch_bounds__(256) void k1(const float* __restrict__ enc,
                                          const float* __restrict__ mask,
                                          const float* __restrict__ subW,
                                          const float* __restrict__ subb,
                                          const float* __restrict__ Wih,
                                          const float* __restrict__ bih) {
    int w = (blockIdx.x * 256 + threadIdx.x) >> 5;
    int lane = threadIdx.x & 31;
    const float4* x4;
    const float4* w4;
    if (w < 256) { x4 = (const float4*)mask; w4 = (const float4*)(subW + (size_t)w * 256); }
    else         { x4 = (const float4*)enc;  w4 = (const float4*)(Wih + (size_t)(w - 256) * 256); }
    float acc = 0.f;
#pragma unroll
    for (int i = 0; i < 2; i++) {
        float4 a = x4[lane + 32 * i];
        float4 b = w4[lane + 32 * i];
        acc += a.x * b.x; acc += a.y * b.y; acc += a.z * b.z; acc += a.w * b.w;
    }
    acc = warp_reduce(acc);
    if (lane == 0) {
        if (w < 256) g_sub[w] = tanhf(acc + subb[w]);
        else         g_gi0[w - 256] = acc + bih[w - 256];
    }
}

// ---------------- K2/K4: GEMV  y[j] = dot(xvec, W[j]) + b[j]  (768 warps) ----------------
// MODE 0: x=g_sub -> g_gh0 (W=Whh,b=bhh);  MODE 1: x=g_r0 -> g_gi (W=Wih,b=bih)
template <int MODE>
__global__ __launch_bounds__(256) void k_gemv768(const float* __restrict__ W,
                                                 const float* __restrict__ b) {
    int j = (blockIdx.x * 256 + threadIdx.x) >> 5;
    int lane = threadIdx.x & 31;
    const float4* x4 = (const float4*)(MODE == 0 ? g_sub : g_r0);
    const float4* w4 = (const float4*)(W + (size_t)j * 256);
    float acc = 0.f;
#pragma unroll
    for (int i = 0; i < 2; i++) {
        float4 a = x4[lane + 32 * i];
        float4 ww = w4[lane + 32 * i];
        acc += a.x * ww.x; acc += a.y * ww.y; acc += a.z * ww.z; acc += a.w * ww.w;
    }
    acc = warp_reduce(acc);
    if (lane == 0) {
        if (MODE == 0) g_gh0[j] = acc + b[j];
        else           g_gi[j]  = acc + b[j];
    }
}

// ---------------- K3: gates -> r0; also write out[seed] = sub ----------------
__global__ void k3(const int* __restrict__ seedp, float* __restrict__ out) {
    int d = threadIdx.x;
    float r = sigmoidf_(g_gi0[d] + g_gh0[d]);
    float z = sigmoidf_(g_gi0[256 + d] + g_gh0[256 + d]);
    float n = tanhf(g_gi0[512 + d] + r * g_gh0[512 + d]);
    float h = g_sub[d];
    g_r0[d] = (1.f - z) * n + z * h;
    out[(size_t)seedp[0] * 256 + d] = h;
}

// ---------------- K5a/K5c: tiled SGEMM  C[R,N] = act(A[R,256] @ B[N,256]^T + bias) ------
// Block tile: 16 rows x 128 cols, k-chunks of 64, per-thread 4x2 register tile, f32x2 FMA.
// MODE 0: A=arg(rel_table) -> g_gh, N=768, no act.  MODE 1: A=g_rj -> g_obj, N=256, tanh.
template <int N, int MODE>
__global__ __launch_bounds__(256) void kgemm(const float* __restrict__ Aarg,
                                             const float* __restrict__ B,
                                             const float* __restrict__ bias,
                                             int R) {
    __shared__ float sh_a[16][64];
    __shared__ ull sh_b[32][129];  // [k2][j] transposed, padded (conflict-light)

    const float* A = (MODE == 0) ? Aarg : g_rj;
    float* C = (MODE == 0) ? g_gh : g_obj;

    int tid = threadIdx.x;
    int relBase = blockIdx.y * 16;
    int jBase = blockIdx.x * 128;
    int tx = tid & 63;   // j lane (j = jBase+tx, jBase+tx+64)
    int ty = tid >> 6;   // row group: rows 4*ty .. 4*ty+3

    ull c[4][2] = {};    // packed (even-k sum, odd-k sum)

    for (int kc = 0; kc < 256; kc += 64) {
        {   // A tile: 16 rows x 64 floats
            int row = tid >> 4, f4 = tid & 15;
            int rel = relBase + row;
            if (rel >= R) rel = R - 1;
            float4 v = *(const float4*)(A + (size_t)rel * 256 + kc + f4 * 4);
            *((float4*)sh_a[row] + f4) = v;
        }
        // B tile: 128 rows x 64 floats, transposed into [k2][j]
#pragma unroll
        for (int i = 0; i < 8; i++) {
            int idx = tid + 256 * i;
            int jrow = idx >> 4, f4 = idx & 15;
            float4 v = *(const float4*)(B + (size_t)(jBase + jrow) * 256 + kc + f4 * 4);
            ull u0 = ((ull)__float_as_uint(v.y) << 32) | (ull)__float_as_uint(v.x);
            ull u1 = ((ull)__float_as_uint(v.w) << 32) | (ull)__float_as_uint(v.z);
            sh_b[f4 * 2][jrow] = u0;
            sh_b[f4 * 2 + 1][jrow] = u1;
        }
        __syncthreads();

        const ull* a0 = (const ull*)sh_a[4 * ty + 0];
        const ull* a1 = (const ull*)sh_a[4 * ty + 1];
        const ull* a2 = (const ull*)sh_a[4 * ty + 2];
        const ull* a3 = (const ull*)sh_a[4 * ty + 3];
#pragma unroll
        for (int k2 = 0; k2 < 32; k2++) {
            ull w0 = sh_b[k2][tx];
            ull w1 = sh_b[k2][tx + 64];
            ull h;
            h = a0[k2]; FMA2(c[0][0], h, w0); FMA2(c[0][1], h, w1);
            h = a1[k2]; FMA2(c[1][0], h, w0); FMA2(c[1][1], h, w1);
            h = a2[k2]; FMA2(c[2][0], h, w0); FMA2(c[2][1], h, w1);
            h = a3[k2]; FMA2(c[3][0], h, w0); FMA2(c[3][1], h, w1);
        }
        __syncthreads();
    }

#pragma unroll
    for (int a = 0; a < 4; a++) {
        int rel = relBase + 4 * ty + a;
        if (rel >= R) continue;
#pragma unroll
        for (int jj = 0; jj < 2; jj++) {
            int j = jBase + tx + jj * 64;
            float lo = __uint_as_float((unsigned)(c[a][jj] & 0xffffffffu));
            float hi = __uint_as_float((unsigned)(c[a][jj] >> 32));
            float s = lo + hi + bias[j];
            if (MODE == 1) s = tanhf(s);
            C[(size_t)rel * N + j] = s;
        }
    }
}

// ---------------- K5b: gates per relation -> g_rj ----------------
__global__ __launch_bounds__(256) void k5b(const float* __restrict__ relT, int R) {
    int rel = blockIdx.x;
    if (rel >= R) return;
    int d = threadIdx.x;
    const float* gh = g_gh + (size_t)rel * 768;
    float r = sigmoidf_(g_gi[d] + gh[d]);
    float z = sigmoidf_(g_gi[256 + d] + gh[256 + d]);
    float n = tanhf(g_gi[512 + d] + r * gh[512 + d]);
    float h = relT[(size_t)rel * 256 + d];
    g_rj[(size_t)rel * 256 + d] = (1.f - z) * n + z * h;
}

// ---------------- K6: per-edge gather/scatter (DRAM-bound) ----------------
// One warp per edge: copy 256 floats (2x float4 per lane). Streaming hints.
__global__ __launch_bounds__(256) void k6(const float* __restrict__ ent,
                                          const int* __restrict__ rel_ids,
                                          const int* __restrict__ tail_ids,
                                          const int* __restrict__ st,
                                          const int* __restrict__ orig,
                                          float* __restrict__ out, int E) {
    int w = (blockIdx.x * 256 + threadIdx.x) >> 5;
    int lane = threadIdx.x & 31;
    if (w >= E) return;
    float4* dst = (float4*)(out + (size_t)tail_ids[w] * 256);
    if (st[w] == 1) {
        const float4* src = (const float4*)(ent + (size_t)orig[w] * 256);
        float4 a = __ldcs(src + lane);
        float4 b = __ldcs(src + lane + 32);
        __stcs(dst + lane, a);
        __stcs(dst + lane + 32, b);
    } else {
        const float4* src = (const float4*)(g_obj + (size_t)rel_ids[w] * 256);
        float4 a = __ldg(src + lane);
        float4 b = __ldg(src + lane + 32);
        __stcs(dst + lane, a);
        __stcs(dst + lane + 32, b);
    }
}

// ---------------- launch ----------------
extern "C" void kernel_launch(void* const* d_in, const int* in_sizes, int n_in,
                              void* d_out, int out_size) {
    const float* enc   = (const float*)d_in[0];
    const float* mask  = (const float*)d_in[1];
    const float* ent   = (const float*)d_in[2];
    const float* relT  = (const float*)d_in[3];
    const float* Wih   = (const float*)d_in[4];
    const float* Whh   = (const float*)d_in[5];
    const float* bih   = (const float*)d_in[6];
    const float* bhh   = (const float*)d_in[7];
    const float* subW  = (const float*)d_in[8];
    const float* subb  = (const float*)d_in[9];
    const float* objW  = (const float*)d_in[10];
    const float* objb  = (const float*)d_in[11];
    const int* rel_ids  = (const int*)d_in[12];
    const int* tail_ids = (const int*)d_in[13];
    const int* tstate   = (const int*)d_in[14];
    const int* orig     = (const int*)d_in[15];
    const int* seedp    = (const int*)d_in[16];
    float* out = (float*)d_out;

    int E = in_sizes[12];
    int R = in_sizes[3] / 256;
    if (R > 1024) R = 1024;

    // tiny GRU chain: sub, gi0 -> gh0 -> gates(r0) -> gi
    k1<<<128, 256>>>(enc, mask, subW, subb, Wih, bih);
    k_gemv768<0><<<96, 256>>>(Whh, bhh);
    k3<<<1, 256>>>(seedp, out);
    k_gemv768<1><<<96, 256>>>(Wih, bih);

    // per-relation table: gh -> rj -> obj
    dim3 g_gh_grid(6, (unsigned)((R + 15) / 16));
    kgemm<768, 0><<<g_gh_grid, 256>>>(relT, Whh, bhh, R);
    k5b<<<R, 256>>>(relT, R);
    dim3 g_obj_grid(2, (unsigned)((R + 15) / 16));
    kgemm<256, 1><<<g_obj_grid, 256>>>(nullptr, objW, objb, R);

    // main scatter
    int blocks = (E + 7) / 8;
    k6<<<blocks, 256>>>(ent, rel_ids, tail_ids, tstate, orig, out, E);
}